// round 4
// baseline (speedup 1.0000x reference)
#include <cuda_runtime.h>

// img:  (1, 64, 64, 1024) float32
// rois: (1, 1024, 4) int32  -> x, y, w, h
// out:  (1, 1024, 7, 7, 1024) float32
//
// One CTA per (roi, py). 256 threads, each owns one float4 channel lane.
// Unrolled px loop with a warp-uniform sliding 2-column register cache to
// dedup bilinear gathers (x coords are nondecreasing across px, and
// x1 <= x0+1, so the two most-recently-loaded columns cover most reuse).
// ydup folds the bottom-row load when y0==y1.

#define POOL 7
#define HW 64
#define CV 256   // float4 lanes per pixel (1024 channels / 4)

__global__ __launch_bounds__(256) void roi_pool_kernel(
    const float* __restrict__ img_,
    const int* __restrict__ rois,
    float* __restrict__ out_)
{
    const float4* __restrict__ img = reinterpret_cast<const float4*>(img_);
    float4* __restrict__ out = reinterpret_cast<float4*>(out_);

    const int py  = blockIdx.x;   // 0..6
    const int roi = blockIdx.y;   // 0..1023

    const int4 r = reinterpret_cast<const int4*>(rois)[roi];
    const int rx = r.x, ry = r.y, rw = r.z, rh = r.w;

    // ---- y axis (computed once per block) ----
    const float sy   = (float)rh / (float)POOL;
    const float srcy = ((float)py + 0.5f) * sy - 0.5f;
    const float fy   = floorf(srcy);
    const float ty   = srcy - fy;
    const int ylo = min(max((int)fy,     0), rh - 1);
    const int yhi = min(max((int)fy + 1, 0), rh - 1);
    const bool ydup = (yhi == ylo);

    const float4* __restrict__ rowT = img + (size_t)(ry + ylo) * HW * CV;
    const float4* __restrict__ rowB = img + (size_t)(ry + yhi) * HW * CV;

    const int c = threadIdx.x;   // channel float4 lane
    float4* __restrict__ o = out + ((size_t)roi * (POOL * POOL) + (size_t)py * POOL) * CV + c;

    const float sx   = (float)rw / (float)POOL;
    const float wty  = ty;
    const float wmty = 1.0f - ty;

    // Sliding cache: two most-recently-loaded columns (warp-uniform state).
    int xp = -1, xq = -1;
    float4 tp = make_float4(0.f,0.f,0.f,0.f), bp = tp, tq = tp, bq = tp;

    #pragma unroll
    for (int px = 0; px < POOL; px++) {
        const float srcx = ((float)px + 0.5f) * sx - 0.5f;
        const float fx   = floorf(srcx);
        const float tx   = srcx - fx;
        const int xlo = min(max((int)fx,     0), rw - 1);
        const int xhi = min(max((int)fx + 1, 0), rw - 1);
        const int xa = rx + xlo;
        const int xb = rx + xhi;

        // fetch column xa (top+bottom)
        float4 ta, ba;
        {
            const bool hq = (xa == xq);
            const bool hp = (xa == xp);
            ta = hq ? tq : tp;
            ba = hq ? bq : bp;
            if (!(hq | hp)) {
                ta = rowT[(size_t)xa * CV + c];
                ba = ydup ? ta : rowB[(size_t)xa * CV + c];
                xp = xq; tp = tq; bp = bq;
                xq = xa; tq = ta; bq = ba;
            }
        }
        // fetch column xb (top+bottom)
        float4 tb, bb;
        {
            const bool hq = (xb == xq);
            const bool hp = (xb == xp);
            tb = hq ? tq : tp;
            bb = hq ? bq : bp;
            if (!(hq | hp)) {
                tb = rowT[(size_t)xb * CV + c];
                bb = ydup ? tb : rowB[(size_t)xb * CV + c];
                xp = xq; tp = tq; bp = bq;
                xq = xb; tq = tb; bq = bb;
            }
        }

        const float wtx  = tx;
        const float wmtx = 1.0f - tx;

        float4 res;
        res.x = (ta.x * wmtx + tb.x * wtx) * wmty + (ba.x * wmtx + bb.x * wtx) * wty;
        res.y = (ta.y * wmtx + tb.y * wtx) * wmty + (ba.y * wmtx + bb.y * wtx) * wty;
        res.z = (ta.z * wmtx + tb.z * wtx) * wmty + (ba.z * wmtx + bb.z * wtx) * wty;
        res.w = (ta.w * wmtx + tb.w * wtx) * wmty + (ba.w * wmtx + bb.w * wtx) * wty;

        o[px * CV] = res;
    }
}

extern "C" void kernel_launch(void* const* d_in, const int* in_sizes, int n_in,
                              void* d_out, int out_size)
{
    const float* img  = (const float*)d_in[0];
    const int*   rois = (const int*)d_in[1];
    float*       out  = (float*)d_out;

    dim3 grid(POOL, 1024);
    roi_pool_kernel<<<grid, 256>>>(img, rois, out);
}

// round 5
// speedup vs baseline: 1.1946x; 1.1946x over previous
#include <cuda_runtime.h>

// img:  (1, 64, 64, 1024) float32
// rois: (1, 1024, 4) int32  -> x, y, w, h
// out:  (1, 1024, 7, 7, 1024) float32
//
// One CTA per (roi, py); 256 threads, one float4 channel lane each.
// Fully unrolled px loop. Duplicate bilinear gathers are skipped with
// PREDICATED loads (inline PTX @p ld.global.nc.v4.f32) -- no branches,
// no BSSY/BSYNC, predicated-off loads consume no L1 wavefront.
// Dedup rules (all warp-uniform predicates):
//   - single most-recent-column cache: xa == previous xb  -> reuse
//   - xb == xa (clip collapse)                            -> reuse
//   - y0 == y1 (ydup)                                     -> bottom = top

#define POOL 7
#define HW 64
#define CV 256   // float4 lanes per pixel

// v keeps its prior value when pred==0 (fallback preloaded by caller).
__device__ __forceinline__ void pred_ld(float4 &v, const float4* __restrict__ p, int pred)
{
    asm("{ .reg .pred %%pq;\n\t"
        "setp.ne.s32 %%pq, %5, 0;\n\t"
        "@%%pq ld.global.nc.v4.f32 {%0,%1,%2,%3}, [%4]; }"
        : "+f"(v.x), "+f"(v.y), "+f"(v.z), "+f"(v.w)
        : "l"(p), "r"(pred));
}

__global__ __launch_bounds__(256) void roi_pool_kernel(
    const float* __restrict__ img_,
    const int* __restrict__ rois,
    float* __restrict__ out_)
{
    const float4* __restrict__ img = reinterpret_cast<const float4*>(img_);
    float4* __restrict__ out = reinterpret_cast<float4*>(out_);

    const int py  = blockIdx.x;   // 0..6
    const int roi = blockIdx.y;   // 0..1023

    const int4 r = reinterpret_cast<const int4*>(rois)[roi];
    const int rx = r.x, ry = r.y, rw = r.z, rh = r.w;

    // ---- y axis (once per block) ----
    const float sy   = (float)rh / (float)POOL;
    const float srcy = ((float)py + 0.5f) * sy - 0.5f;
    const float fy   = floorf(srcy);
    const float ty   = srcy - fy;
    const int ylo = min(max((int)fy,     0), rh - 1);
    const int yhi = min(max((int)fy + 1, 0), rh - 1);
    const int noty = (yhi != ylo);   // 0 => bottom row == top row

    const float4* __restrict__ rowT = img + (size_t)((ry + ylo) * HW) * CV;
    const float4* __restrict__ rowB = img + (size_t)((ry + yhi) * HW) * CV;

    const int c = threadIdx.x;
    float4* __restrict__ o = out + ((size_t)roi * (POOL * POOL) + (size_t)py * POOL) * CV + c;

    const float sx   = (float)rw / (float)POOL;
    const float wty  = ty;
    const float wmty = 1.0f - ty;

    int xprev = -1;
    float4 tprev = make_float4(0.f, 0.f, 0.f, 0.f);
    float4 bprev = tprev;

    #pragma unroll
    for (int px = 0; px < POOL; px++) {
        const float srcx = ((float)px + 0.5f) * sx - 0.5f;
        const float fx   = floorf(srcx);
        const float tx   = srcx - fx;
        const int xlo = min(max((int)fx,     0), rw - 1);
        const int xhi = min(max((int)fx + 1, 0), rw - 1);
        const int xa = rx + xlo;
        const int xb = rx + xhi;

        const int pa = (xa != xprev);
        const int pb = (xb != xa);

        // column A
        float4 ta = tprev;
        pred_ld(ta, rowT + (size_t)xa * CV + c, pa);
        float4 ba = pa ? ta : bprev;             // covers (pa && ydup) and (!pa)
        pred_ld(ba, rowB + (size_t)xa * CV + c, pa & noty);

        // column B
        float4 tb = ta;                          // fallback when xb==xa
        pred_ld(tb, rowT + (size_t)xb * CV + c, pb);
        float4 bb = pb ? tb : ba;
        pred_ld(bb, rowB + (size_t)xb * CV + c, pb & noty);

        const float wtx  = tx;
        const float wmtx = 1.0f - tx;

        float4 res;
        res.x = (ta.x * wmtx + tb.x * wtx) * wmty + (ba.x * wmtx + bb.x * wtx) * wty;
        res.y = (ta.y * wmtx + tb.y * wtx) * wmty + (ba.y * wmtx + bb.y * wtx) * wty;
        res.z = (ta.z * wmtx + tb.z * wtx) * wmty + (ba.z * wmtx + bb.z * wtx) * wty;
        res.w = (ta.w * wmtx + tb.w * wtx) * wmty + (ba.w * wmtx + bb.w * wtx) * wty;

        o[px * CV] = res;

        xprev = xb;
        tprev = tb;
        bprev = bb;
    }
}

extern "C" void kernel_launch(void* const* d_in, const int* in_sizes, int n_in,
                              void* d_out, int out_size)
{
    const float* img  = (const float*)d_in[0];
    const int*   rois = (const int*)d_in[1];
    float*       out  = (float*)d_out;

    dim3 grid(POOL, 1024);
    roi_pool_kernel<<<grid, 256>>>(img, rois, out);
}